// round 3
// baseline (speedup 1.0000x reference)
#include <cuda_runtime.h>
#include <stdint.h>

#define BN      16384
#define IN_DIM  256
#define HID     128
#define NCLS    8
#define T_STEPS 64
#define BETA    0.9f

// Scratch (no cudaMalloc allowed)
__device__ float g_cur1[BN * HID];          // 8 MB   cur1 = x@W1^T + b1
__device__ uint4 g_masks[T_STEPS * BN];     // 16 MB  [t][sample] 128-bit spike masks
__device__ float g_W1T[IN_DIM * HID];       // 128 KB W1 transposed: [k][h]

// ---------------------------------------------------------------------------
// K0: W1T[k][h] = W1[h][k]   (one-time tiny transpose, 32768 elements)
// ---------------------------------------------------------------------------
__global__ __launch_bounds__(256) void k0_w1t(const float* __restrict__ W1)
{
    int idx = blockIdx.x * 256 + threadIdx.x;      // 0..32767
    int h = idx & (HID - 1);
    int k = idx >> 7;
    g_W1T[k * HID + h] = W1[h * IN_DIM + k];       // write coalesced
}

// ---------------------------------------------------------------------------
// K1: cur1[s][h] = sum_k x[s][k] * W1[h][k] + b1[h]
// CTA tile: 64 samples x 128 hid. K chunks of 32. 256 threads, 8s x 4h/thread.
// Both smem tiles stored with STS.128 (no scatter transposes).
// ---------------------------------------------------------------------------
#define XS_STRIDE 36   // floats per x-tile row (16B-aligned, conflict-free reads)

__global__ __launch_bounds__(256) void k1_fc1(const float* __restrict__ x,
                                              const float* __restrict__ b1)
{
    __shared__ float xs[64 * XS_STRIDE];   // [s][k]  9216 B
    __shared__ float ws[32 * HID];         // [k][h]  16 KB

    const int tid = threadIdx.x;
    const int bs  = blockIdx.x * 64;
    const int c   = tid & 7;               // sample lane 0..7 (samples c + 8j)
    const int r   = tid >> 3;              // hid group 0..31 (hid r*4 + i)

    // global load addresses (2 x-float4s, 4 w-float4s per thread per chunk)
    const int xf0_s  = (2 * 0 * 256 + tid) >> 3, xf0_k = ((2 * 0 * 256 + tid) & 7) * 4;
    const int xf1_s  = (256 + tid) >> 3,         xf1_k = ((256 + tid) & 7) * 4;

    float4 px0, px1, pw[4];

    // prefetch chunk 0
    {
        px0 = *(const float4*)&x[(bs + xf0_s) * IN_DIM + xf0_k];
        px1 = *(const float4*)&x[(bs + xf1_s) * IN_DIM + xf1_k];
#pragma unroll
        for (int i = 0; i < 4; i++) {
            int f  = i * 256 + tid;
            int kk = f >> 5;
            int h4 = (f & 31) * 4;
            pw[i] = *(const float4*)&g_W1T[kk * HID + h4];
        }
    }

    float acc[4][8];
#pragma unroll
    for (int i = 0; i < 4; i++)
#pragma unroll
        for (int j = 0; j < 8; j++) acc[i][j] = 0.0f;

    for (int ch = 0; ch < IN_DIM / 32; ch++) {
        // store prefetched tile
        *(float4*)&xs[xf0_s * XS_STRIDE + xf0_k] = px0;
        *(float4*)&xs[xf1_s * XS_STRIDE + xf1_k] = px1;
#pragma unroll
        for (int i = 0; i < 4; i++) {
            int f  = i * 256 + tid;
            int kk = f >> 5;
            int h4 = (f & 31) * 4;
            *(float4*)&ws[kk * HID + h4] = pw[i];
        }
        __syncthreads();

        // prefetch next chunk while computing this one
        if (ch + 1 < IN_DIM / 32) {
            int kc = (ch + 1) * 32;
            px0 = *(const float4*)&x[(bs + xf0_s) * IN_DIM + kc + xf0_k];
            px1 = *(const float4*)&x[(bs + xf1_s) * IN_DIM + kc + xf1_k];
#pragma unroll
            for (int i = 0; i < 4; i++) {
                int f  = i * 256 + tid;
                int kk = f >> 5;
                int h4 = (f & 31) * 4;
                pw[i] = *(const float4*)&g_W1T[(kc + kk) * HID + h4];
            }
        }

#pragma unroll
        for (int k = 0; k < 32; k += 4) {
            float4 xv[8];
#pragma unroll
            for (int j = 0; j < 8; j++)
                xv[j] = *(const float4*)&xs[(c + 8 * j) * XS_STRIDE + k];
            float4 wv[4];
#pragma unroll
            for (int kk = 0; kk < 4; kk++)
                wv[kk] = *(const float4*)&ws[(k + kk) * HID + r * 4];
#pragma unroll
            for (int kk = 0; kk < 4; kk++) {
                float w0 = wv[kk].x, w1 = wv[kk].y, w2 = wv[kk].z, w3 = wv[kk].w;
#pragma unroll
                for (int j = 0; j < 8; j++) {
                    float xvk = (kk == 0) ? xv[j].x : (kk == 1) ? xv[j].y
                              : (kk == 2) ? xv[j].z : xv[j].w;
                    acc[0][j] = fmaf(w0, xvk, acc[0][j]);
                    acc[1][j] = fmaf(w1, xvk, acc[1][j]);
                    acc[2][j] = fmaf(w2, xvk, acc[2][j]);
                    acc[3][j] = fmaf(w3, xvk, acc[3][j]);
                }
            }
        }
        __syncthreads();
    }

    float4 b1v = *(const float4*)&b1[r * 4];
#pragma unroll
    for (int j = 0; j < 8; j++) {
        int s = bs + c + 8 * j;
        float4 o;
        o.x = acc[0][j] + b1v.x;
        o.y = acc[1][j] + b1v.y;
        o.z = acc[2][j] + b1v.z;
        o.w = acc[3][j] + b1v.w;
        *(float4*)&g_cur1[s * HID + r * 4] = o;
    }
}

// ---------------------------------------------------------------------------
// K2: layer-1 LIF recurrence + spike mask packing (ballot).
// Warp = one 32-hid group x 4 samples. Block = 8 warps = 8 samples.
// ---------------------------------------------------------------------------
__global__ __launch_bounds__(256) void k2_lif1()
{
    __shared__ uint32_t sm[T_STEPS][8][4];   // [t][sampleLocal][group] = 8 KB

    const int tid  = threadIdx.x;
    const int w    = tid >> 5;
    const int lane = tid & 31;
    const int g    = w & 3;      // hid group
    const int q    = w >> 2;     // sample quad 0/1
    const int sb   = blockIdx.x * 8 + q * 4;
    const int h    = g * 32 + lane;

    float cur[4], mem[4];
#pragma unroll
    for (int j = 0; j < 4; j++) {
        cur[j] = g_cur1[(sb + j) * HID + h];
        mem[j] = 0.0f;
    }

    for (int t = 0; t < T_STEPS; t++) {
#pragma unroll
        for (int j = 0; j < 4; j++) {
            float m  = mem[j];
            float rf = (m > 1.0f) ? 1.0f : 0.0f;            // reset from incoming mem
            m = fmaf(BETA, m, cur[j]) - rf;
            mem[j] = m;
            unsigned bal = __ballot_sync(0xffffffffu, m > 1.0f);
            if (lane == 0) sm[t][q * 4 + j][g] = bal;
        }
    }
    __syncthreads();

    for (int idx = tid; idx < T_STEPS * 8; idx += 256) {
        int t  = idx >> 3;
        int sl = idx & 7;
        g_masks[t * BN + blockIdx.x * 8 + sl] = *(const uint4*)&sm[t][sl][0];
    }
}

// ---------------------------------------------------------------------------
// K3: layer-2 via byte-pattern LUT. 4 lanes per sample; lane j owns mask word
// j (chunks 4j..4j+3), pair-reduction via shfl_xor leaves lane j with classes
// {2j, 2j+1}. 512 threads/CTA, 128 CTAs, 128 KB smem LUT.
// ---------------------------------------------------------------------------
__global__ __launch_bounds__(512) void k3_lif2(const float* __restrict__ W2,
                                               const float* __restrict__ b2,
                                               float* __restrict__ out)
{
    extern __shared__ float lut[];   // [16][256][8] = 128 KB
    const int tid = threadIdx.x;

    for (int e = tid; e < 16 * 256; e += 512) {
        int chunk = e >> 8;
        int byte  = e & 255;
        float v[8];
#pragma unroll
        for (int cc = 0; cc < 8; cc++) v[cc] = 0.0f;
#pragma unroll
        for (int j = 0; j < 8; j++) {
            if ((byte >> j) & 1) {
#pragma unroll
                for (int cc = 0; cc < 8; cc++)
                    v[cc] += W2[cc * HID + chunk * 8 + j];
            }
        }
#pragma unroll
        for (int cc = 0; cc < 8; cc++) lut[e * 8 + cc] = v[cc];
    }
    __syncthreads();

    const int lane = tid & 31;
    const int j    = lane & 3;                       // lane within sample
    const int s    = blockIdx.x * 128 + (tid >> 2);  // sample

    // this lane's two classes: {2j, 2j+1}
    const float b2a = b2[2 * j];
    const float b2b = b2[2 * j + 1];

    float memA = 0.0f, memB = 0.0f, accA = 0.0f, accB = 0.0f;
    float rfA = 0.0f, rfB = 0.0f;

    const uint32_t* mw = (const uint32_t*)g_masks;
    const unsigned FULL = 0xffffffffu;

    for (int t = 0; t < T_STEPS; t++) {
        uint32_t wv = mw[(size_t)(t * BN + s) * 4 + j];

        // 4 lookups, classes 0-3 in A, 4-7 in B
        float4 A = make_float4(0.f, 0.f, 0.f, 0.f);
        float4 Bv = make_float4(0.f, 0.f, 0.f, 0.f);
#pragma unroll
        for (int b = 0; b < 4; b++) {
            int idx = ((((j * 4 + b) << 8) | ((wv >> (8 * b)) & 255)) << 3);
            float4 p0 = *(const float4*)&lut[idx];
            float4 p1 = *(const float4*)&lut[idx + 4];
            A.x += p0.x;  A.y += p0.y;  A.z += p0.z;  A.w += p0.w;
            Bv.x += p1.x; Bv.y += p1.y; Bv.z += p1.z; Bv.w += p1.w;
        }

        // round 1 (xor 2): exchange class-halves so lanes 0,1 own classes 0-3
        // and lanes 2,3 own classes 4-7 (each still partial over chunks).
        float4 snd = (j & 2) ? A : Bv;    // send the half I do NOT keep
        float4 kp  = (j & 2) ? Bv : A;    // keep my half
        float4 rc;
        rc.x = __shfl_xor_sync(FULL, snd.x, 2);
        rc.y = __shfl_xor_sync(FULL, snd.y, 2);
        rc.z = __shfl_xor_sync(FULL, snd.z, 2);
        rc.w = __shfl_xor_sync(FULL, snd.w, 2);
        kp.x += rc.x; kp.y += rc.y; kp.z += rc.z; kp.w += rc.w;

        // round 2 (xor 1): sum complementary chunk halves -> full 16 chunks
        kp.x += __shfl_xor_sync(FULL, kp.x, 1);
        kp.y += __shfl_xor_sync(FULL, kp.y, 1);
        kp.z += __shfl_xor_sync(FULL, kp.z, 1);
        kp.w += __shfl_xor_sync(FULL, kp.w, 1);

        // pick my 2 classes
        float curA = ((j & 1) ? kp.z : kp.x) + b2a;
        float curB = ((j & 1) ? kp.w : kp.y) + b2b;

        // LIF (reset = previous post-update spike)
        memA = fmaf(BETA, memA, curA) - rfA;
        memB = fmaf(BETA, memB, curB) - rfB;
        rfA = (memA > 1.0f) ? 1.0f : 0.0f;
        rfB = (memB > 1.0f) ? 1.0f : 0.0f;
        accA += rfA;
        accB += rfB;
    }

    *(float2*)&out[s * 8 + 2 * j] = make_float2(accA, accB);
}

// ---------------------------------------------------------------------------
extern "C" void kernel_launch(void* const* d_in, const int* in_sizes, int n_in,
                              void* d_out, int out_size)
{
    const float* x  = (const float*)d_in[0];
    const float* W1 = (const float*)d_in[1];
    const float* b1 = (const float*)d_in[2];
    const float* W2 = (const float*)d_in[3];
    const float* b2 = (const float*)d_in[4];
    float* out = (float*)d_out;

    k0_w1t<<<(IN_DIM * HID) / 256, 256>>>(W1);
    k1_fc1<<<BN / 64, 256>>>(x, b1);
    k2_lif1<<<BN / 8, 256>>>();

    cudaFuncSetAttribute(k3_lif2, cudaFuncAttributeMaxDynamicSharedMemorySize, 131072);
    k3_lif2<<<BN / 128, 512, 131072>>>(W2, b2, out);
}

// round 4
// speedup vs baseline: 1.3532x; 1.3532x over previous
#include <cuda_runtime.h>
#include <stdint.h>

#define BN      16384
#define IN_DIM  256
#define HID     128
#define NCLS    8
#define T_STEPS 64
#define BETA    0.9f

// Scratch (no cudaMalloc allowed)
__device__ float g_cur1[BN * HID];          // 8 MB   cur1 = x@W1^T + b1
__device__ uint4 g_masks[T_STEPS * BN];     // 16 MB  [t][sample] 128-bit spike masks
__device__ float g_W1T[IN_DIM * HID];       // 128 KB W1 transposed: [k][h]

// ---------------------------------------------------------------------------
// K0: W1T[k][h] = W1[h][k]
// ---------------------------------------------------------------------------
__global__ __launch_bounds__(256) void k0_w1t(const float* __restrict__ W1)
{
    int idx = blockIdx.x * 256 + threadIdx.x;
    int h = idx & (HID - 1);
    int k = idx >> 7;
    g_W1T[k * HID + h] = W1[h * IN_DIM + k];
}

// ---------------------------------------------------------------------------
// K1: cur1[s][h] = sum_k x[s][k] * W1[h][k] + b1[h]
// CTA tile: 64 samples x 128 hid. K chunks of 32. 256 threads, 8s x 4h/thread.
// ---------------------------------------------------------------------------
#define XS_STRIDE 36

__global__ __launch_bounds__(256) void k1_fc1(const float* __restrict__ x,
                                              const float* __restrict__ b1)
{
    __shared__ float xs[64 * XS_STRIDE];
    __shared__ float ws[32 * HID];

    const int tid = threadIdx.x;
    const int bs  = blockIdx.x * 64;
    const int c   = tid & 7;
    const int r   = tid >> 3;

    const int xf0_s = tid >> 3,         xf0_k = (tid & 7) * 4;
    const int xf1_s = (256 + tid) >> 3, xf1_k = ((256 + tid) & 7) * 4;

    float4 px0, px1, pw[4];

    px0 = *(const float4*)&x[(bs + xf0_s) * IN_DIM + xf0_k];
    px1 = *(const float4*)&x[(bs + xf1_s) * IN_DIM + xf1_k];
#pragma unroll
    for (int i = 0; i < 4; i++) {
        int f  = i * 256 + tid;
        int kk = f >> 5;
        int h4 = (f & 31) * 4;
        pw[i] = *(const float4*)&g_W1T[kk * HID + h4];
    }

    float acc[4][8];
#pragma unroll
    for (int i = 0; i < 4; i++)
#pragma unroll
        for (int j = 0; j < 8; j++) acc[i][j] = 0.0f;

    for (int ch = 0; ch < IN_DIM / 32; ch++) {
        *(float4*)&xs[xf0_s * XS_STRIDE + xf0_k] = px0;
        *(float4*)&xs[xf1_s * XS_STRIDE + xf1_k] = px1;
#pragma unroll
        for (int i = 0; i < 4; i++) {
            int f  = i * 256 + tid;
            int kk = f >> 5;
            int h4 = (f & 31) * 4;
            *(float4*)&ws[kk * HID + h4] = pw[i];
        }
        __syncthreads();

        if (ch + 1 < IN_DIM / 32) {
            int kc = (ch + 1) * 32;
            px0 = *(const float4*)&x[(bs + xf0_s) * IN_DIM + kc + xf0_k];
            px1 = *(const float4*)&x[(bs + xf1_s) * IN_DIM + kc + xf1_k];
#pragma unroll
            for (int i = 0; i < 4; i++) {
                int f  = i * 256 + tid;
                int kk = f >> 5;
                int h4 = (f & 31) * 4;
                pw[i] = *(const float4*)&g_W1T[(kc + kk) * HID + h4];
            }
        }

#pragma unroll
        for (int k = 0; k < 32; k += 4) {
            float4 xv[8];
#pragma unroll
            for (int j = 0; j < 8; j++)
                xv[j] = *(const float4*)&xs[(c + 8 * j) * XS_STRIDE + k];
            float4 wv[4];
#pragma unroll
            for (int kk = 0; kk < 4; kk++)
                wv[kk] = *(const float4*)&ws[(k + kk) * HID + r * 4];
#pragma unroll
            for (int kk = 0; kk < 4; kk++) {
                float w0 = wv[kk].x, w1 = wv[kk].y, w2 = wv[kk].z, w3 = wv[kk].w;
#pragma unroll
                for (int j = 0; j < 8; j++) {
                    float xvk = (kk == 0) ? xv[j].x : (kk == 1) ? xv[j].y
                              : (kk == 2) ? xv[j].z : xv[j].w;
                    acc[0][j] = fmaf(w0, xvk, acc[0][j]);
                    acc[1][j] = fmaf(w1, xvk, acc[1][j]);
                    acc[2][j] = fmaf(w2, xvk, acc[2][j]);
                    acc[3][j] = fmaf(w3, xvk, acc[3][j]);
                }
            }
        }
        __syncthreads();
    }

    float4 b1v = *(const float4*)&b1[r * 4];
#pragma unroll
    for (int j = 0; j < 8; j++) {
        int s = bs + c + 8 * j;
        float4 o;
        o.x = acc[0][j] + b1v.x;
        o.y = acc[1][j] + b1v.y;
        o.z = acc[2][j] + b1v.z;
        o.w = acc[3][j] + b1v.w;
        *(float4*)&g_cur1[s * HID + r * 4] = o;
    }
}

// ---------------------------------------------------------------------------
// K2: layer-1 LIF recurrence + spike mask packing (ballot).
// ---------------------------------------------------------------------------
__global__ __launch_bounds__(256) void k2_lif1()
{
    __shared__ uint32_t sm[T_STEPS][8][4];

    const int tid  = threadIdx.x;
    const int w    = tid >> 5;
    const int lane = tid & 31;
    const int g    = w & 3;
    const int q    = w >> 2;
    const int sb   = blockIdx.x * 8 + q * 4;
    const int h    = g * 32 + lane;

    float cur[4], mem[4];
#pragma unroll
    for (int j = 0; j < 4; j++) {
        cur[j] = g_cur1[(sb + j) * HID + h];
        mem[j] = 0.0f;
    }

    for (int t = 0; t < T_STEPS; t++) {
#pragma unroll
        for (int j = 0; j < 4; j++) {
            float m  = mem[j];
            float rf = (m > 1.0f) ? 1.0f : 0.0f;
            m = fmaf(BETA, m, cur[j]) - rf;
            mem[j] = m;
            unsigned bal = __ballot_sync(0xffffffffu, m > 1.0f);
            if (lane == 0) sm[t][q * 4 + j][g] = bal;
        }
    }
    __syncthreads();

    for (int idx = tid; idx < T_STEPS * 8; idx += 256) {
        int t  = idx >> 3;
        int sl = idx & 7;
        g_masks[t * BN + blockIdx.x * 8 + sl] = *(const uint4*)&sm[t][sl][0];
    }
}

// ---------------------------------------------------------------------------
// K3: layer-2 LIF via byte-pattern LUT, split by class half.
// CTA pair per 128-sample block: blockIdx bit0 selects classes 0-3 or 4-7.
// LUT[16][256][4] = 64 KB dyn smem -> 2 CTAs/SM. One thread per sample,
// no shuffles, mask prefetch distance 2. 256 CTAs x 128 threads.
// ---------------------------------------------------------------------------
static __device__ __forceinline__ float4 f4add(float4 a, float4 b)
{
    return make_float4(a.x + b.x, a.y + b.y, a.z + b.z, a.w + b.w);
}

__global__ __launch_bounds__(128) void k3_lif2(const float* __restrict__ W2,
                                               const float* __restrict__ b2,
                                               float* __restrict__ out)
{
    extern __shared__ float lut[];   // [16][256][4] floats = 64 KB
    const int tid   = threadIdx.x;
    const int chalf = blockIdx.x & 1;            // class half: 0 -> 0-3, 1 -> 4-7
    const int s     = (blockIdx.x >> 1) * 128 + tid;

    // build LUT for my 4 classes
    for (int e = tid; e < 16 * 256; e += 128) {
        int chunk = e >> 8;
        int byt   = e & 255;
        float v0 = 0.f, v1 = 0.f, v2 = 0.f, v3 = 0.f;
#pragma unroll
        for (int j = 0; j < 8; j++) {
            if ((byt >> j) & 1) {
                int h = chunk * 8 + j;
                v0 += W2[(chalf * 4 + 0) * HID + h];
                v1 += W2[(chalf * 4 + 1) * HID + h];
                v2 += W2[(chalf * 4 + 2) * HID + h];
                v3 += W2[(chalf * 4 + 3) * HID + h];
            }
        }
        *(float4*)&lut[e * 4] = make_float4(v0, v1, v2, v3);
    }
    __syncthreads();

    float4 b2v = make_float4(b2[chalf * 4 + 0], b2[chalf * 4 + 1],
                             b2[chalf * 4 + 2], b2[chalf * 4 + 3]);

    const uint4* mp = &g_masks[s];   // [t][B]: stride BN, coalesced across warp

    uint4 m0 = mp[0];
    uint4 m1 = mp[BN];

    float4 mem = make_float4(0.f, 0.f, 0.f, 0.f);
    float4 acc = mem, rst = mem;

    for (int t = 0; t < T_STEPS; t++) {
        uint4 m = m0;
        m0 = m1;
        if (t + 2 < T_STEPS) m1 = mp[(size_t)(t + 2) * BN];

        uint32_t w[4] = {m.x, m.y, m.z, m.w};
        float4 sg[4];
#pragma unroll
        for (int g = 0; g < 4; g++) {
            const float* lg = &lut[g * 4096];    // 4 chunks of this mask word
            uint32_t wg = w[g];
            float4 q0 = *(const float4*)&lg[          ((wg       & 255u) << 2)];
            float4 q1 = *(const float4*)&lg[1 * 1024 + (((wg >> 8) & 255u) << 2)];
            float4 q2 = *(const float4*)&lg[2 * 1024 + (((wg >> 16) & 255u) << 2)];
            float4 q3 = *(const float4*)&lg[3 * 1024 + ((wg >> 24) << 2)];
            sg[g] = f4add(f4add(q0, q1), f4add(q2, q3));
        }
        float4 cur = f4add(f4add(f4add(sg[0], sg[1]), f4add(sg[2], sg[3])), b2v);

        mem.x = fmaf(BETA, mem.x, cur.x) - rst.x;
        mem.y = fmaf(BETA, mem.y, cur.y) - rst.y;
        mem.z = fmaf(BETA, mem.z, cur.z) - rst.z;
        mem.w = fmaf(BETA, mem.w, cur.w) - rst.w;
        rst.x = (mem.x > 1.0f) ? 1.0f : 0.0f;
        rst.y = (mem.y > 1.0f) ? 1.0f : 0.0f;
        rst.z = (mem.z > 1.0f) ? 1.0f : 0.0f;
        rst.w = (mem.w > 1.0f) ? 1.0f : 0.0f;
        acc.x += rst.x; acc.y += rst.y; acc.z += rst.z; acc.w += rst.w;
    }

    *(float4*)&out[s * 8 + chalf * 4] = acc;
}

// ---------------------------------------------------------------------------
extern "C" void kernel_launch(void* const* d_in, const int* in_sizes, int n_in,
                              void* d_out, int out_size)
{
    const float* x  = (const float*)d_in[0];
    const float* W1 = (const float*)d_in[1];
    const float* b1 = (const float*)d_in[2];
    const float* W2 = (const float*)d_in[3];
    const float* b2 = (const float*)d_in[4];
    float* out = (float*)d_out;

    k0_w1t<<<(IN_DIM * HID) / 256, 256>>>(W1);
    k1_fc1<<<BN / 64, 256>>>(x, b1);
    k2_lif1<<<BN / 8, 256>>>();

    cudaFuncSetAttribute(k3_lif2, cudaFuncAttributeMaxDynamicSharedMemorySize, 65536);
    k3_lif2<<<(BN / 128) * 2, 128, 65536>>>(W2, b2, out);
}